// round 6
// baseline (speedup 1.0000x reference)
#include <cuda_runtime.h>
#include <cstdint>

#define BB 512
#define RR 264
#define KK 32
#define SS 9
#define KST 268            // sT k-row stride in floats (1072 B)
#define NTHREADS 256
#define NCG 33             // 8-wide col groups
#define NRG 33             // 8-tall row groups
#define CELLS (NRG * NCG)  // 1089
#define NITERS 5           // ceil(1089/256)

typedef unsigned long long ull;

__device__ __constant__ int c_ends[SS]   = {28, 58, 92, 121, 150, 180, 210, 240, 264};
__device__ __constant__ int c_starts[SS] = {0, 28, 58, 92, 121, 150, 180, 210, 240};
__device__ __constant__ float c_sizes[SS] = {28.f, 30.f, 34.f, 29.f, 29.f, 30.f, 30.f, 30.f, 24.f};

__device__ __forceinline__ ull fma2(ull a, ull b, ull c) {
    ull d;
    asm("fma.rn.f32x2 %0, %1, %2, %3;" : "=l"(d) : "l"(a), "l"(b), "l"(c));
    return d;
}
__device__ __forceinline__ ull dup2(float x) {
    ull d;
    asm("mov.b64 %0, {%1, %1};" : "=l"(d) : "f"(x));
    return d;
}
__device__ __forceinline__ float2 unpack2(ull v) {
    float2 r;
    asm("mov.b64 {%0, %1}, %2;" : "=f"(r.x), "=f"(r.y) : "l"(v));
    return r;
}

extern "C" __global__ void __launch_bounds__(NTHREADS, 2)
gram_kernel(const float* __restrict__ E, float* __restrict__ out)
{
    float* intra = out;
    float* inter = out + (size_t)BB * RR * RR;
    float* adj   = inter + (size_t)BB * SS * SS;

    __shared__ float sT[KK * KST];   // E[b]^T : sT[k*KST + r]
    __shared__ int2  sLoHi[RR];      // per-row segment range [lo, hi)
    __shared__ float sSum[SS * KK];

    const int b   = blockIdx.x;
    const int tid = threadIdx.x;
    const float* Eb = E + (size_t)b * (RR * KK);

    // ---- transpose-load E[b] into smem ----
    for (int i = tid; i < (RR * KK) / 4; i += NTHREADS) {
        float4 v = reinterpret_cast<const float4*>(Eb)[i];
        int row = i >> 3, k4 = (i & 7) << 2;
        sT[(k4 + 0) * KST + row] = v.x;
        sT[(k4 + 1) * KST + row] = v.y;
        sT[(k4 + 2) * KST + row] = v.z;
        sT[(k4 + 3) * KST + row] = v.w;
    }
    for (int r = tid; r < RR; r += NTHREADS) {
        int s = 0;
        #pragma unroll
        for (int j = 0; j < SS; j++) s += (r >= c_ends[j]) ? 1 : 0;
        sLoHi[r] = make_int2(c_starts[s], c_ends[s]);
    }
    __syncthreads();

    // ---- inter-network block means (every CTA owns one batch) ----
    for (int i = tid; i < SS * KK; i += NTHREADS) {
        int s  = i >> 5;
        int d  = i & 31;
        int st = (s == 0) ? 0 : c_ends[s - 1];
        int en = c_ends[s];
        float a = 0.0f;
        const float* kp = &sT[d * KST];
        for (int r = st; r < en; r++) a += kp[r];
        sSum[i] = a;
    }
    __syncthreads();
    if (tid < SS * SS) {
        int s = tid / SS, t = tid % SS;
        float a = 0.0f;
        #pragma unroll
        for (int d = 0; d < KK; d++)
            a += sSum[s * KK + d] * sSum[t * KK + d];
        inter[(size_t)b * SS * SS + tid] = a / (c_sizes[s] * c_sizes[t]);
    }

    // ---- main: 8x8 register-tiled cells ----
    for (int it = 0; it < NITERS; it++) {
        const int m = it * NTHREADS + tid;
        const bool valid = (m < CELLS);
        const int mm = valid ? m : 0;
        const int ci = mm / NCG;
        const int cj = mm - ci * NCG;
        const int r0 = ci * 8;
        const int c0 = cj * 8;

        ull acc[8][4];
        #pragma unroll
        for (int i = 0; i < 8; i++)
            #pragma unroll
            for (int j = 0; j < 4; j++) acc[i][j] = 0ull;

        #pragma unroll 4
        for (int k = 0; k < KK; k++) {
            const float* kp = &sT[k * KST];
            float4 a0 = *reinterpret_cast<const float4*>(kp + r0);       // rows (bcast)
            float4 a1 = *reinterpret_cast<const float4*>(kp + r0 + 4);
            ulonglong2 b0 = *reinterpret_cast<const ulonglong2*>(kp + c0);     // col-pairs
            ulonglong2 b1 = *reinterpret_cast<const ulonglong2*>(kp + c0 + 4);
            ull bv0 = b0.x, bv1 = b0.y, bv2 = b1.x, bv3 = b1.y;
            float av[8] = {a0.x, a0.y, a0.z, a0.w, a1.x, a1.y, a1.z, a1.w};
            #pragma unroll
            for (int ri = 0; ri < 8; ri++) {
                ull ad = dup2(av[ri]);
                acc[ri][0] = fma2(ad, bv0, acc[ri][0]);
                acc[ri][1] = fma2(ad, bv1, acc[ri][1]);
                acc[ri][2] = fma2(ad, bv2, acc[ri][2]);
                acc[ri][3] = fma2(ad, bv3, acc[ri][3]);
            }
        }

        if (valid) {
            float* abase = adj   + (((size_t)b * RR + r0) * RR) + c0;
            float* ibase = intra + (((size_t)b * RR + r0) * RR) + c0;
            #pragma unroll
            for (int ri = 0; ri < 8; ri++) {
                const int r = r0 + ri;
                const int2 lh = sLoHi[r];       // broadcast LDS.64
                float2 p0 = unpack2(acc[ri][0]);
                float2 p1 = unpack2(acc[ri][1]);
                float2 p2 = unpack2(acc[ri][2]);
                float2 p3 = unpack2(acc[ri][3]);
                float4 v0; v0.x = p0.x; v0.y = p0.y; v0.z = p1.x; v0.w = p1.y;
                float4 v1; v1.x = p2.x; v1.y = p2.y; v1.z = p3.x; v1.w = p3.y;
                *reinterpret_cast<float4*>(abase + (size_t)ri * RR)     = v0;
                *reinterpret_cast<float4*>(abase + (size_t)ri * RR + 4) = v1;
                float4 w0, w1;
                w0.x = (c0 + 0 >= lh.x && c0 + 0 < lh.y) ? v0.x : 0.0f;
                w0.y = (c0 + 1 >= lh.x && c0 + 1 < lh.y) ? v0.y : 0.0f;
                w0.z = (c0 + 2 >= lh.x && c0 + 2 < lh.y) ? v0.z : 0.0f;
                w0.w = (c0 + 3 >= lh.x && c0 + 3 < lh.y) ? v0.w : 0.0f;
                w1.x = (c0 + 4 >= lh.x && c0 + 4 < lh.y) ? v1.x : 0.0f;
                w1.y = (c0 + 5 >= lh.x && c0 + 5 < lh.y) ? v1.y : 0.0f;
                w1.z = (c0 + 6 >= lh.x && c0 + 6 < lh.y) ? v1.z : 0.0f;
                w1.w = (c0 + 7 >= lh.x && c0 + 7 < lh.y) ? v1.w : 0.0f;
                *reinterpret_cast<float4*>(ibase + (size_t)ri * RR)     = w0;
                *reinterpret_cast<float4*>(ibase + (size_t)ri * RR + 4) = w1;
            }
        }
    }
}

extern "C" void kernel_launch(void* const* d_in, const int* in_sizes, int n_in,
                              void* d_out, int out_size)
{
    (void)in_sizes; (void)n_in; (void)out_size;
    const float* E = (const float*)d_in[0];
    float* out = (float*)d_out;

    gram_kernel<<<BB, NTHREADS>>>(E, out);
}